// round 3
// baseline (speedup 1.0000x reference)
#include <cuda_runtime.h>
#include <cuda_fp16.h>
#include <cstdint>

// ---------------------------------------------------------------------------
// PHMLinear via Kronecker factorization, warp-level HMMA (baseline PTX, no
// tcgen05 -- ptxas here targets plain sm_103 which rejects 'a' features).
//
//   Per token (X = x row viewed 64x64):  Y = sum_b A_b @ X @ B_b^T + bias
//   computed as U_b = A_b @ X (contract j), Y += U_b @ B_b^T (contract m).
//   U_b stays in registers: mma m16n8k16 C-fragment == next A-fragment (FA2).
// ---------------------------------------------------------------------------

#define TILES 4096        // 4 tokens per tile, 16384 tokens total

#define OFF_A    0        // 512 rows x 128B, fp16 A[(b,i), j], swizzled
#define OFF_B    65536    // 512 rows x 128B, fp16 B[(b,k), m], swizzled
#define OFF_BIAS 131072   // 4096 fp32
#define OFF_X    147456   // 4 tokens x 64 rows x 128B, fp16 X[(t,j), m]
#define SMEM_BYTES 180224

__device__ __forceinline__ uint32_t swz(uint32_t o) { return o ^ ((o >> 3) & 0x70); }

__device__ __forceinline__ uint32_t s2u(const void* p) {
    uint32_t a;
    asm("{ .reg .u64 t; cvta.to.shared.u64 t, %1; cvt.u32.u64 %0, t; }" : "=r"(a) : "l"(p));
    return a;
}
__device__ __forceinline__ uint32_t h2u(__half2 h) { return *reinterpret_cast<uint32_t*>(&h); }

__device__ __forceinline__ void ldsm4(uint32_t a, uint32_t* r) {
    asm volatile("ldmatrix.sync.aligned.m8n8.x4.shared.b16 {%0,%1,%2,%3}, [%4];"
                 : "=r"(r[0]), "=r"(r[1]), "=r"(r[2]), "=r"(r[3]) : "r"(a));
}
__device__ __forceinline__ void ldsm4t(uint32_t a, uint32_t* r) {
    asm volatile("ldmatrix.sync.aligned.m8n8.x4.trans.shared.b16 {%0,%1,%2,%3}, [%4];"
                 : "=r"(r[0]), "=r"(r[1]), "=r"(r[2]), "=r"(r[3]) : "r"(a));
}
__device__ __forceinline__ void mma16816(float* d, const uint32_t* a, const uint32_t* b) {
    asm volatile(
        "mma.sync.aligned.m16n8k16.row.col.f32.f16.f16.f32 "
        "{%0,%1,%2,%3}, {%4,%5,%6,%7}, {%8,%9}, {%0,%1,%2,%3};"
        : "+f"(d[0]), "+f"(d[1]), "+f"(d[2]), "+f"(d[3])
        : "r"(a[0]), "r"(a[1]), "r"(a[2]), "r"(a[3]), "r"(b[0]), "r"(b[1]));
}

extern __shared__ char smem[];

__global__ void __launch_bounds__(256, 1)
phm_kernel(const float* __restrict__ x, const float* __restrict__ A,
           const float* __restrict__ B, const float* __restrict__ bias,
           float* __restrict__ out)
{
    const int tid  = threadIdx.x;
    const int wid  = tid >> 5;
    const int lane = tid & 31;
    const uint32_t sbase = s2u(smem);

    // ---- one-time: weights fp32 -> fp16 swizzled smem, bias fp32 smem ----
    {
        const float4* Ag = (const float4*)A;   // 8192 float4
        const float4* Bg = (const float4*)B;
        #pragma unroll
        for (int p = 0; p < 32; p++) {
            int v = tid + (p << 8);
            int row = v >> 4, m4 = v & 15;
            uint32_t off = swz((uint32_t)(row * 128 + m4 * 8));
            float4 f = Ag[v];
            *(uint2*)(smem + OFF_A + off) =
                make_uint2(h2u(__floats2half2_rn(f.x, f.y)), h2u(__floats2half2_rn(f.z, f.w)));
            f = Bg[v];
            *(uint2*)(smem + OFF_B + off) =
                make_uint2(h2u(__floats2half2_rn(f.x, f.y)), h2u(__floats2half2_rn(f.z, f.w)));
        }
        const float4* bg = (const float4*)bias;
        #pragma unroll
        for (int p = 0; p < 4; p++) {
            int v = tid + (p << 8);
            *(float4*)(smem + OFF_BIAS + v * 16) = bg[v];
        }
    }

    const int tl    = wid >> 1;        // token slot 0..3 within tile
    const int ihalf = wid & 1;         // which 32 rows of i
    const int ibase = ihalf << 5;
    const int l16   = lane & 15;       // ldmatrix row component (A, X patterns)
    const int lhi   = lane >> 4;       // ldmatrix col-half component
    const int b2row = ((lane >> 4) << 3) + (lane & 7);   // B2 pattern row part
    const int b2c   = (lane >> 3) & 1;                   // B2 pattern col part
    const int gi    = lane >> 2;       // mma group row
    const int gk    = (lane & 3) << 1; // mma group col pair

    const uint32_t Xt = sbase + OFF_X + tl * 8192;

    for (int tile = blockIdx.x; tile < TILES; tile += (int)gridDim.x) {
        __syncthreads();   // previous compute done reading X
        // ---- stage X: 4 tokens fp32 -> fp16 swizzled ----
        const float4* xg = (const float4*)(x + (size_t)tile * 16384);
        #pragma unroll
        for (int p = 0; p < 16; p++) {
            int v = tid + (p << 8);          // 0..4095 float4s
            float4 f = xg[v];
            int w = v & 1023, row = w >> 4, m4 = w & 15;
            uint32_t off = (uint32_t)((v >> 10) * 8192) + swz((uint32_t)(row * 128 + m4 * 8));
            *(uint2*)(smem + OFF_X + off) =
                make_uint2(h2u(__floats2half2_rn(f.x, f.y)), h2u(__floats2half2_rn(f.z, f.w)));
        }
        __syncthreads();

        // ---- init Y with bias ----
        float Y[2][8][4];
        #pragma unroll
        for (int rt = 0; rt < 2; rt++) {
            int i0 = ibase + rt * 16 + gi;
            #pragma unroll
            for (int nt = 0; nt < 8; nt++) {
                int k0 = nt * 8 + gk;
                float2 b01 = *(const float2*)(smem + OFF_BIAS + (size_t)(i0 * 64 + k0) * 4);
                float2 b23 = *(const float2*)(smem + OFF_BIAS + (size_t)((i0 + 8) * 64 + k0) * 4);
                Y[rt][nt][0] = b01.x; Y[rt][nt][1] = b01.y;
                Y[rt][nt][2] = b23.x; Y[rt][nt][3] = b23.y;
            }
        }

        #pragma unroll
        for (int mc = 0; mc < 2; mc++) {
            // cache X B-fragments for this m-chunk (shared across all b)
            uint32_t XB[4][2][4];
            #pragma unroll
            for (int jt = 0; jt < 4; jt++) {
                int row = jt * 16 + l16;
                #pragma unroll
                for (int ntp = 0; ntp < 2; ntp++) {
                    uint32_t c = (uint32_t)(mc * 4 + ntp * 2 + lhi) ^ (uint32_t)(row & 7);
                    ldsm4t(Xt + (uint32_t)(row * 128) + (c << 4), XB[jt][ntp]);
                }
            }
            #pragma unroll
            for (int b = 0; b < 8; b++) {
                // ---- GEMM1: U = A_b[ibase:ibase+32, :] @ X[:, mc*32:+32] ----
                float U[2][4][4];
                #pragma unroll
                for (int rt = 0; rt < 2; rt++)
                    #pragma unroll
                    for (int nt = 0; nt < 4; nt++)
                        #pragma unroll
                        for (int e = 0; e < 4; e++) U[rt][nt][e] = 0.f;

                #pragma unroll
                for (int jt = 0; jt < 4; jt++) {
                    uint32_t AF[2][4];
                    #pragma unroll
                    for (int rt = 0; rt < 2; rt++) {
                        int row = b * 64 + ibase + rt * 16 + l16;
                        uint32_t c = (uint32_t)(jt * 2 + lhi) ^ (uint32_t)(row & 7);
                        ldsm4(sbase + OFF_A + (uint32_t)(row * 128) + (c << 4), AF[rt]);
                    }
                    #pragma unroll
                    for (int rt = 0; rt < 2; rt++)
                        #pragma unroll
                        for (int nt = 0; nt < 4; nt++)
                            mma16816(U[rt][nt], AF[rt], XB[jt][nt >> 1] + (nt & 1) * 2);
                }
                // ---- convert U (f32 C-frags) -> GEMM2 A-frags (f16) ----
                uint32_t UA[2][2][4];
                #pragma unroll
                for (int rt = 0; rt < 2; rt++)
                    #pragma unroll
                    for (int mt = 0; mt < 2; mt++) {
                        UA[rt][mt][0] = h2u(__floats2half2_rn(U[rt][2*mt][0],   U[rt][2*mt][1]));
                        UA[rt][mt][1] = h2u(__floats2half2_rn(U[rt][2*mt][2],   U[rt][2*mt][3]));
                        UA[rt][mt][2] = h2u(__floats2half2_rn(U[rt][2*mt+1][0], U[rt][2*mt+1][1]));
                        UA[rt][mt][3] = h2u(__floats2half2_rn(U[rt][2*mt+1][2], U[rt][2*mt+1][3]));
                    }
                // ---- GEMM2: Y += U @ B_b[:, mc*32:+32]^T ----
                #pragma unroll
                for (int kop = 0; kop < 4; kop++) {
                    uint32_t BF[2][4];
                    #pragma unroll
                    for (int mt = 0; mt < 2; mt++) {
                        int row = b * 64 + kop * 16 + b2row;
                        uint32_t c = (uint32_t)(mc * 4 + mt * 2 + b2c) ^ (uint32_t)(lane & 7);
                        ldsm4(sbase + OFF_B + (uint32_t)(row * 128) + (c << 4), BF[mt]);
                    }
                    #pragma unroll
                    for (int mt = 0; mt < 2; mt++)
                        #pragma unroll
                        for (int rt = 0; rt < 2; rt++)
                            #pragma unroll
                            for (int h = 0; h < 2; h++)
                                mma16816(Y[rt][kop * 2 + h], UA[rt][mt], BF[mt] + h * 2);
                }
            }
        }

        // ---- store Y (bias already included) ----
        float* orow = out + ((size_t)tile * 4 + tl) * 4096;
        #pragma unroll
        for (int rt = 0; rt < 2; rt++) {
            int i0 = ibase + rt * 16 + gi;
            #pragma unroll
            for (int nt = 0; nt < 8; nt++) {
                int k0 = nt * 8 + gk;
                *(float2*)(orow + (size_t)i0 * 64 + k0)       = make_float2(Y[rt][nt][0], Y[rt][nt][1]);
                *(float2*)(orow + (size_t)(i0 + 8) * 64 + k0) = make_float2(Y[rt][nt][2], Y[rt][nt][3]);
            }
        }
    }
}

extern "C" void kernel_launch(void* const* d_in, const int* in_sizes, int n_in,
                              void* d_out, int out_size) {
    const float* x    = (const float*)d_in[0];
    const float* A    = (const float*)d_in[1];
    const float* B    = (const float*)d_in[2];
    const float* bias = (const float*)d_in[3];
    float* out        = (float*)d_out;

    cudaFuncSetAttribute(phm_kernel, cudaFuncAttributeMaxDynamicSharedMemorySize, SMEM_BYTES);
    int nsm = 148;
    cudaDeviceGetAttribute(&nsm, cudaDevAttrMultiProcessorCount, 0);
    if (nsm <= 0 || nsm > 1024) nsm = 148;
    if (nsm > TILES) nsm = TILES;

    phm_kernel<<<nsm, 256, SMEM_BYTES>>>(x, A, B, bias, out);
}